// round 8
// baseline (speedup 1.0000x reference)
#include <cuda_runtime.h>
#include <math.h>

// Problem constants
#define DD 128
#define TT 512
#define HH 512

// 4 groups x 32 CTAs; group g owns batches [64g, 64g+64).
// CTA c owns h-columns [16c,16c+16) and z-columns [4c,4c+4).
#define NGROUP 4
#define CPG 32
#define MB 64
#define NCTA (NGROUP * CPG)
#define NTHREADS 512
#define KT 64
#define NTILE (HH / KT)          // 8 staged h tiles per step

// smem layout (floats):
//   Ws4: packed W_hh slice, [k][tx] float4 {wr,wz,wn,0}  -> 512*64
//   Wi4: packed W_ih slice                                -> 128*64
//   Wf : fc_W slice [k][cd]                               -> 512*4
//   hs : ping-pong activation tiles (2 x 64x64)           -> 8192
#define SM_WS 0
#define SM_WI (SM_WS + HH * 64)
#define SM_WF (SM_WI + DD * 64)
#define SM_HS (SM_WF + HH * 4)
#define SM_FLOATS (SM_HS + 2 * KT * MB)
#define SMEM_BYTES (SM_FLOATS * 4)          // 204,800 B

// Global state (zero-initialized at module load)
__device__ __align__(16) float g_hbuf[NGROUP * HH * MB];  // [g][k][b]
__device__ __align__(16) float g_zbuf[NGROUP * DD * MB];  // [g][col][b]
__device__ unsigned g_cnt[NGROUP];
__device__ volatile unsigned g_gen[NGROUP];

#define CP_COMMIT() asm volatile("cp.async.commit_group;\n" ::: "memory")
#define CP_WAIT(n)  asm volatile("cp.async.wait_group %0;\n" :: "n"(n) : "memory")

__device__ __forceinline__ void stage_async(float *dst, const float *src, int n4) {
    const float4 *s4 = (const float4 *)src;
    float4 *d4 = (float4 *)dst;
    for (int i = threadIdx.x; i < n4; i += NTHREADS) {
        unsigned sa = (unsigned)__cvta_generic_to_shared(d4 + i);
        asm volatile("cp.async.cg.shared.global [%0], [%1], 16;\n"
                     :: "r"(sa), "l"(s4 + i) : "memory");
    }
}

// Sense-reversing group barrier across 32 co-resident CTAs.
__device__ __forceinline__ void group_barrier(int g, unsigned &next_gen) {
    __syncthreads();
    if (threadIdx.x == 0) {
        __threadfence();                       // publish our global writes
        unsigned prev = atomicAdd(&g_cnt[g], 1u);
        if (prev == CPG - 1) {
            g_cnt[g] = 0;
            __threadfence();
            g_gen[g] = next_gen;               // release
        } else {
            while ((int)(g_gen[g] - next_gen) < 0) { }
        }
        __threadfence();                       // acquire
    }
    next_gen++;
    __syncthreads();
}

__global__ __launch_bounds__(NTHREADS, 1)
void gru_decoder_kernel(const float *__restrict__ z_in,
                        const float *__restrict__ W_ih,
                        const float *__restrict__ W_hh,
                        const float *__restrict__ b_ih,
                        const float *__restrict__ b_hh,
                        const float *__restrict__ fc_W,
                        const float *__restrict__ fc_b,
                        float *__restrict__ out) {
    extern __shared__ float sm[];
    float *Ws4 = sm + SM_WS;
    float *Wi4 = sm + SM_WI;
    float *Wf  = sm + SM_WF;
    float *hs  = sm + SM_HS;

    const int tid = threadIdx.x;
    const int c = blockIdx.x & (CPG - 1);
    const int g = blockIdx.x >> 5;
    const int tx = tid & 15;              // owned j (within the 16-slice)
    const int ty = tid >> 4;              // 0..31: batch pair {2ty, 2ty+1}
    const int jg = 16 * c + tx;
    const bool isd = (tid < 256);         // delta duty: warps 0..7 only
    const int b_d = tid & 63;
    const int cd = (tid >> 6) & 3;
    const int colg = 4 * c + cd;
    const int b0 = g * MB;

    // ---- stage + pack weight slices (one-time) ----
    for (int r = 0; r < 48; ++r) {
        const int gate = r >> 4, txv = r & 15;
        const float *src = W_hh + (gate * HH + 16 * c + txv) * HH;
        for (int k = tid; k < HH; k += NTHREADS)
            Ws4[k * 64 + txv * 4 + gate] = src[k];
    }
    for (int r = 0; r < 48; ++r) {
        const int gate = r >> 4, txv = r & 15;
        const float *src = W_ih + (gate * HH + 16 * c + txv) * DD;
        for (int k = tid; k < DD; k += NTHREADS)
            Wi4[k * 64 + txv * 4 + gate] = src[k];
    }
    for (int idx = tid; idx < HH * 16; idx += NTHREADS) Ws4[idx * 4 + 3] = 0.f;
    for (int idx = tid; idx < DD * 16; idx += NTHREADS) Wi4[idx * 4 + 3] = 0.f;
    for (int rr = 0; rr < 4; ++rr) {
        const float *src = fc_W + (4 * c + rr) * HH;
        for (int k = tid; k < HH; k += NTHREADS) Wf[k * 4 + rr] = src[k];
    }

    // ---- per-thread constants ----
    const float br_s  = b_ih[jg] + b_hh[jg];
    const float bz_s  = b_ih[HH + jg] + b_hh[HH + jg];
    const float bin_s = b_ih[2 * HH + jg];
    const float bhn_s = b_hh[2 * HH + jg];

    float fcb = 0.f, z_reg = 0.f;
    if (isd) {
        fcb = fc_b[colg];
        z_reg = z_in[(b0 + b_d) * (DD * TT) + colg * TT];
        g_zbuf[(g * DD + colg) * MB + b_d] = z_reg;
        out[(b0 + b_d) * (DD * TT) + colg * TT] = z_reg;
    }
    float hprev0 = 0.f, hprev1 = 0.f;

    unsigned next_gen = g_gen[g] + 1;  // stable: no release can precede all arrivals
    group_barrier(g, next_gen);        // zbuf visible group-wide

    const float *hbuf = g_hbuf + g * HH * MB;
    const float *zbuf = g_zbuf + g * DD * MB;
    const float4 *Wsv = (const float4 *)Ws4;
    const float4 *Wiv = (const float4 *)Wi4;

    for (int t = 1; t <= TT; ++t) {
        float accr0 = br_s,  accr1 = br_s;
        float accz0 = bz_s,  accz1 = bz_s;
        float acchn0 = bhn_s, acchn1 = bhn_s;
        float accin0 = bin_s, accin1 = bin_s;
        float dacc = fcb;

        // ---- h-pass: gh_t and delta_{t-1}, double-buffered staging ----
        if (t > 1) {
            stage_async(hs, hbuf, KT * MB / 4);
            CP_COMMIT();
            for (int it = 0; it < NTILE; ++it) {
                if (it + 1 < NTILE) {
                    stage_async(hs + ((it + 1) & 1) * (KT * MB),
                                hbuf + (it + 1) * (KT * MB), KT * MB / 4);
                    CP_COMMIT();
                    CP_WAIT(1);
                } else {
                    CP_WAIT(0);
                }
                __syncthreads();

                const float *hb = hs + (it & 1) * (KT * MB);
                const float2 *h2p = (const float2 *)hb;
                const float4 *wp = Wsv + it * (KT * 16);
                const float *wfp = Wf + it * (KT * 4);

                if (isd) {
#pragma unroll 16
                    for (int kk = 0; kk < KT; ++kk) {
                        const float4 w4 = wp[kk * 16 + tx];
                        const float2 h2 = h2p[kk * 32 + ty];
                        accr0  += w4.x * h2.x; accr1  += w4.x * h2.y;
                        accz0  += w4.y * h2.x; accz1  += w4.y * h2.y;
                        acchn0 += w4.z * h2.x; acchn1 += w4.z * h2.y;
                        dacc += wfp[kk * 4 + cd] * hb[kk * MB + b_d];
                    }
                } else {
#pragma unroll 16
                    for (int kk = 0; kk < KT; ++kk) {
                        const float4 w4 = wp[kk * 16 + tx];
                        const float2 h2 = h2p[kk * 32 + ty];
                        accr0  += w4.x * h2.x; accr1  += w4.x * h2.y;
                        accz0  += w4.y * h2.x; accz1  += w4.y * h2.y;
                        acchn0 += w4.z * h2.x; acchn1 += w4.z * h2.y;
                    }
                }
                __syncthreads();
            }
            if (isd) {
                z_reg += dacc;
                g_zbuf[(g * DD + colg) * MB + b_d] = z_reg;
                out[(b0 + b_d) * (DD * TT) + colg * TT + (t - 1)] = z_reg;
            }
        }

        group_barrier(g, next_gen);   // z_{t-1} complete group-wide

        if (t < TT) {
            // ---- z-pass: gi_t over full z_{t-1} (one 8 KB stage) ----
            stage_async(hs, zbuf, DD * MB / 4);
            CP_COMMIT();
            CP_WAIT(0);
            __syncthreads();

            const float2 *x2p = (const float2 *)hs;
#pragma unroll 16
            for (int kk = 0; kk < DD; ++kk) {
                const float4 w4 = Wiv[kk * 16 + tx];
                const float2 x2 = x2p[kk * 32 + ty];
                accr0  += w4.x * x2.x; accr1  += w4.x * x2.y;
                accz0  += w4.y * x2.x; accz1  += w4.y * x2.y;
                accin0 += w4.z * x2.x; accin1 += w4.z * x2.y;
            }

            // ---- gates + h update (2 batches, registers) ----
            const float r0 = 1.f / (1.f + expf(-accr0));
            const float r1 = 1.f / (1.f + expf(-accr1));
            const float zz0 = 1.f / (1.f + expf(-accz0));
            const float zz1 = 1.f / (1.f + expf(-accz1));
            const float n0 = tanhf(accin0 + r0 * acchn0);
            const float n1 = tanhf(accin1 + r1 * acchn1);
            const float h0 = (1.f - zz0) * n0 + zz0 * hprev0;
            const float h1 = (1.f - zz1) * n1 + zz1 * hprev1;
            hprev0 = h0; hprev1 = h1;
            float *hw = g_hbuf + (g * HH + jg) * MB + 2 * ty;
            hw[0] = h0; hw[1] = h1;
        }

        group_barrier(g, next_gen);   // h_t complete group-wide
    }
}

extern "C" void kernel_launch(void* const* d_in, const int* in_sizes, int n_in,
                              void* d_out, int out_size) {
    (void)in_sizes; (void)n_in; (void)out_size;
    const float *z    = (const float *)d_in[0];
    // d_in[1] = e (unused by the reference computation)
    const float *W_ih = (const float *)d_in[2];
    const float *W_hh = (const float *)d_in[3];
    const float *b_ih = (const float *)d_in[4];
    const float *b_hh = (const float *)d_in[5];
    const float *fc_W = (const float *)d_in[6];
    const float *fc_b = (const float *)d_in[7];
    float *out = (float *)d_out;

    cudaFuncSetAttribute(gru_decoder_kernel,
                         cudaFuncAttributeMaxDynamicSharedMemorySize, SMEM_BYTES);
    gru_decoder_kernel<<<NCTA, NTHREADS, SMEM_BYTES>>>(
        z, W_ih, W_hh, b_ih, b_hh, fc_W, fc_b, out);
}

// round 11
// speedup vs baseline: 1.3352x; 1.3352x over previous
#include <cuda_runtime.h>
#include <math.h>

// Problem constants
#define DD 128
#define TT 512
#define HH 512

// 4 groups x 32 CTAs; group g owns batches [64g, 64g+64).
// CTA c owns h-columns [16c,16c+16) and z-columns [4c,4c+4).
#define NGROUP 4
#define CPG 32
#define MB 64
#define NCTA (NGROUP * CPG)
#define NTHREADS 256
#define KT 64
#define NTILE (HH / KT)          // 8 staged h tiles per step

// smem layout (floats):
//   Ws4: packed W_hh slice [k][tx] float4 {wr,wz,wn,0}   -> 512*64
//   Wi4: packed W_ih slice                                -> 128*64
//   Wf : fc_W slice [k][cd]                               -> 512*4
//   hs : ping-pong activation tiles (2 x 64x64)           -> 8192
#define SM_WS 0
#define SM_WI (SM_WS + HH * 64)
#define SM_WF (SM_WI + DD * 64)
#define SM_HS (SM_WF + HH * 4)
#define SM_FLOATS (SM_HS + 2 * KT * MB)
#define SMEM_BYTES (SM_FLOATS * 4)          // 204,800 B

// Global state (zero-initialized at module load)
__device__ __align__(16) float g_hbuf[NGROUP * HH * MB];  // [g][k][b]
__device__ __align__(16) float g_zbuf[NGROUP * DD * MB];  // [g][col][b]
__device__ unsigned g_cnt[NGROUP];
__device__ volatile unsigned g_gen[NGROUP];

#define CP_COMMIT() asm volatile("cp.async.commit_group;\n" ::: "memory")
#define CP_WAIT(n)  asm volatile("cp.async.wait_group %0;\n" :: "n"(n) : "memory")

__device__ __forceinline__ void stage_async(float *dst, const float *src, int n4) {
    const float4 *s4 = (const float4 *)src;
    float4 *d4 = (float4 *)dst;
    for (int i = threadIdx.x; i < n4; i += NTHREADS) {
        unsigned sa = (unsigned)__cvta_generic_to_shared(d4 + i);
        asm volatile("cp.async.cg.shared.global [%0], [%1], 16;\n"
                     :: "r"(sa), "l"(s4 + i) : "memory");
    }
}

// Sense-reversing group barrier across 32 co-resident CTAs.
// Release-side fence only: all cross-CTA data reads after the barrier go
// through L2 (cp.async.cg / volatile), so no L1-invalidate acquire is needed.
__device__ __forceinline__ void group_barrier(int g, unsigned &next_gen) {
    __syncthreads();
    if (threadIdx.x == 0) {
        __threadfence();                       // publish our global writes
        unsigned prev = atomicAdd(&g_cnt[g], 1u);
        if (prev == CPG - 1) {
            g_cnt[g] = 0;
            __threadfence();
            g_gen[g] = next_gen;               // release
        } else {
            while ((int)(g_gen[g] - next_gen) < 0) { }
        }
    }
    next_gen++;
    __syncthreads();
}

__global__ __launch_bounds__(NTHREADS, 1)
void gru_decoder_kernel(const float *__restrict__ z_in,
                        const float *__restrict__ W_ih,
                        const float *__restrict__ W_hh,
                        const float *__restrict__ b_ih,
                        const float *__restrict__ b_hh,
                        const float *__restrict__ fc_W,
                        const float *__restrict__ fc_b,
                        float *__restrict__ out) {
    extern __shared__ float sm[];
    float *Ws4 = sm + SM_WS;
    float *Wi4 = sm + SM_WI;
    float *Wf  = sm + SM_WF;
    float *hs  = sm + SM_HS;

    const int tid = threadIdx.x;
    const int c = blockIdx.x & (CPG - 1);
    const int g = blockIdx.x >> 5;
    const int tx = tid & 15;              // owned j (within the 16-slice)
    const int ty = tid >> 4;              // 0..15: batch quad {4ty..4ty+3}
    const int jg = 16 * c + tx;
    const int b_d = tid & 63;             // delta batch
    const int cd = tid >> 6;              // delta col (0..3)
    const int colg = 4 * c + cd;
    const int b0 = g * MB;

    // ---- stage + pack weight slices (one-time) ----
    for (int r = 0; r < 48; ++r) {
        const int gate = r >> 4, txv = r & 15;
        const float *src = W_hh + (gate * HH + 16 * c + txv) * HH;
        for (int k = tid; k < HH; k += NTHREADS)
            Ws4[k * 64 + txv * 4 + gate] = src[k];
    }
    for (int r = 0; r < 48; ++r) {
        const int gate = r >> 4, txv = r & 15;
        const float *src = W_ih + (gate * HH + 16 * c + txv) * DD;
        for (int k = tid; k < DD; k += NTHREADS)
            Wi4[k * 64 + txv * 4 + gate] = src[k];
    }
    for (int idx = tid; idx < HH * 16; idx += NTHREADS) Ws4[idx * 4 + 3] = 0.f;
    for (int idx = tid; idx < DD * 16; idx += NTHREADS) Wi4[idx * 4 + 3] = 0.f;
    for (int rr = 0; rr < 4; ++rr) {
        const float *src = fc_W + (4 * c + rr) * HH;
        for (int k = tid; k < HH; k += NTHREADS) Wf[k * 4 + rr] = src[k];
    }

    // ---- per-thread constants ----
    const float br_s  = b_ih[jg] + b_hh[jg];
    const float bz_s  = b_ih[HH + jg] + b_hh[HH + jg];
    const float bin_s = b_ih[2 * HH + jg];
    const float bhn_s = b_hh[2 * HH + jg];
    const float fcb   = fc_b[colg];

    // ---- z0 init ----
    float z_reg = z_in[(b0 + b_d) * (DD * TT) + colg * TT];
    g_zbuf[(g * DD + colg) * MB + b_d] = z_reg;
    out[(b0 + b_d) * (DD * TT) + colg * TT] = z_reg;

    float hprev[4] = {0.f, 0.f, 0.f, 0.f};

    unsigned next_gen = g_gen[g] + 1;  // stable snapshot: release needs all arrivals
    group_barrier(g, next_gen);        // zbuf visible group-wide

    const float *hbuf = g_hbuf + g * HH * MB;
    const float *zbuf = g_zbuf + g * DD * MB;
    const float4 *Wsv = (const float4 *)Ws4;
    const float4 *Wiv = (const float4 *)Wi4;

    for (int t = 1; t <= TT; ++t) {
        float accr[4]  = {br_s, br_s, br_s, br_s};
        float accz[4]  = {bz_s, bz_s, bz_s, bz_s};
        float acchn[4] = {bhn_s, bhn_s, bhn_s, bhn_s};
        float accin[4] = {bin_s, bin_s, bin_s, bin_s};
        float dacc = fcb;

        // ---- h-pass: gh_t and delta_{t-1}, double-buffered cp.async tiles ----
        if (t > 1) {
            stage_async(hs, hbuf, KT * MB / 4);
            CP_COMMIT();
            for (int it = 0; it < NTILE; ++it) {
                if (it + 1 < NTILE) {
                    stage_async(hs + ((it + 1) & 1) * (KT * MB),
                                hbuf + (it + 1) * (KT * MB), KT * MB / 4);
                    CP_COMMIT();
                    CP_WAIT(1);
                } else {
                    CP_WAIT(0);
                }
                __syncthreads();   // tile `it` data visible to all threads

                const float *hb = hs + (it & 1) * (KT * MB);
                const float4 *h4p = (const float4 *)hb;
                const float4 *wp = Wsv + it * (KT * 16);
                const float *wfp = Wf + it * (KT * 4);

#pragma unroll 8
                for (int kk = 0; kk < KT; ++kk) {
                    const float4 w4 = wp[kk * 16 + tx];
                    const float4 h4 = h4p[kk * 16 + ty];
                    const float hd = hb[kk * MB + b_d];
                    const float wf = wfp[kk * 4 + cd];
                    accr[0]  += w4.x * h4.x; accr[1]  += w4.x * h4.y;
                    accr[2]  += w4.x * h4.z; accr[3]  += w4.x * h4.w;
                    accz[0]  += w4.y * h4.x; accz[1]  += w4.y * h4.y;
                    accz[2]  += w4.y * h4.z; accz[3]  += w4.y * h4.w;
                    acchn[0] += w4.z * h4.x; acchn[1] += w4.z * h4.y;
                    acchn[2] += w4.z * h4.z; acchn[3] += w4.z * h4.w;
                    dacc += wf * hd;
                }
                __syncthreads();   // reads done before this buffer is re-staged
            }
            z_reg += dacc;
            g_zbuf[(g * DD + colg) * MB + b_d] = z_reg;
            out[(b0 + b_d) * (DD * TT) + colg * TT + (t - 1)] = z_reg;
        }

        group_barrier(g, next_gen);   // z_{t-1} complete group-wide

        if (t < TT) {
            // ---- z-pass: gi_t over full z_{t-1} (32 KB stage into both bufs) ----
            stage_async(hs, zbuf, DD * MB / 4);
            CP_COMMIT();
            CP_WAIT(0);
            __syncthreads();

            const float4 *x4p = (const float4 *)hs;
#pragma unroll 8
            for (int kk = 0; kk < DD; ++kk) {
                const float4 w4 = Wiv[kk * 16 + tx];
                const float4 x4 = x4p[kk * 16 + ty];
                accr[0]  += w4.x * x4.x; accr[1]  += w4.x * x4.y;
                accr[2]  += w4.x * x4.z; accr[3]  += w4.x * x4.w;
                accz[0]  += w4.y * x4.x; accz[1]  += w4.y * x4.y;
                accz[2]  += w4.y * x4.z; accz[3]  += w4.y * x4.w;
                accin[0] += w4.z * x4.x; accin[1] += w4.z * x4.y;
                accin[2] += w4.z * x4.z; accin[3] += w4.z * x4.w;
            }

            // ---- gates + h update (owned slice in registers) ----
#pragma unroll
            for (int i = 0; i < 4; ++i) {
                const float r  = 1.0f / (1.0f + expf(-accr[i]));
                const float zg = 1.0f / (1.0f + expf(-accz[i]));
                const float n  = tanhf(accin[i] + r * acchn[i]);
                const float h  = (1.0f - zg) * n + zg * hprev[i];
                hprev[i] = h;
                g_hbuf[(g * HH + jg) * MB + 4 * ty + i] = h;
            }
        }

        group_barrier(g, next_gen);   // h_t complete group-wide
    }
}

extern "C" void kernel_launch(void* const* d_in, const int* in_sizes, int n_in,
                              void* d_out, int out_size) {
    (void)in_sizes; (void)n_in; (void)out_size;
    const float *z    = (const float *)d_in[0];
    // d_in[1] = e (unused by the reference computation)
    const float *W_ih = (const float *)d_in[2];
    const float *W_hh = (const float *)d_in[3];
    const float *b_ih = (const float *)d_in[4];
    const float *b_hh = (const float *)d_in[5];
    const float *fc_W = (const float *)d_in[6];
    const float *fc_b = (const float *)d_in[7];
    float *out = (float *)d_out;

    cudaFuncSetAttribute(gru_decoder_kernel,
                         cudaFuncAttributeMaxDynamicSharedMemorySize, SMEM_BYTES);
    gru_decoder_kernel<<<NCTA, NTHREADS, SMEM_BYTES>>>(
        z, W_ih, W_hh, b_ih, b_hh, fc_W, fc_b, out);
}